// round 2
// baseline (speedup 1.0000x reference)
#include <cuda_runtime.h>
#include <math.h>

// Problem dimensions (fixed by the reference setup_inputs)
#define TOKENS 16384   // B*S = 8*2048
#define Dd 1024
#define Hh 2048
#define Aa 128
#define Ss 2048
#define Bb 8

// ---------------- scratch (device globals; no allocation allowed) ----------
__device__ float g_gate  [(size_t)TOKENS * Hh];   // 134 MB
__device__ float g_hidden[(size_t)TOKENS * Hh];   // 134 MB
__device__ float g_pre   [(size_t)TOKENS * Aa];
__device__ float g_ain   [(size_t)TOKENS * Aa];
__device__ float g_aout  [(size_t)TOKENS * Aa];
__device__ float g_adapt [(size_t)TOKENS * Aa];
__device__ float g_abuf  [(size_t)TOKENS * Aa];
__device__ float g_aw    [(size_t)Bb * Ss * Ss];  // 134 MB
__device__ float g_W     [(size_t)Dd * Aa];       // w_out @ w_eproj

// ---------------- helpers --------------------------------------------------
__device__ __forceinline__ float siluf(float x) {
    return x / (1.0f + __expf(-x));
}
__device__ __forceinline__ float clip5(float x) {
    return fminf(fmaxf(x, -5.0f), 5.0f);
}

// ---------------- generic tiled SGEMM: C = A(MxK) * op(B) --------------------
// BT=true : B is [N,K] row-major (NT gemm, C[m,n] = sum_k A[m,k]*B[n,k])
// BT=false: B is [K,N] row-major (NN gemm)
// EPI 0: C = acc
// EPI 1: C = silu(clip(acc))
// EPI 2: C = silu(Ex) * acc            (hidden = silu(gate)*up)
// EPI 3: C = Ex + 0.1f * acc           (in-place accumulate allowed, Ex may == C)
constexpr int BM = 128, BN = 128, BK = 16;

template <bool BT, int EPI>
__global__ void __launch_bounds__(256)
gemm_kernel(const float* __restrict__ Ag, const float* __restrict__ Bg,
            const float* __restrict__ Eg, float* __restrict__ Cg,
            int M, int N, int K,
            long long sA, long long sB, long long sC)
{
    const float* A = Ag + (long long)blockIdx.z * sA;
    const float* B = Bg + (long long)blockIdx.z * sB;
    float*       C = Cg + (long long)blockIdx.z * sC;
    const float* Ex = (EPI == 2 || EPI == 3) ? (Eg + (long long)blockIdx.z * sC) : nullptr;

    __shared__ float As[BK][BM];
    __shared__ float Bs[BK][BN];

    const int tid = threadIdx.x;
    const int tx = tid & 15;        // 0..15
    const int ty = tid >> 4;        // 0..15
    const int m0 = blockIdx.y * BM;
    const int n0 = blockIdx.x * BN;

    float acc[8][8];
#pragma unroll
    for (int i = 0; i < 8; i++)
#pragma unroll
        for (int j = 0; j < 8; j++) acc[i][j] = 0.0f;

    for (int k0 = 0; k0 < K; k0 += BK) {
        // ---- load A tile (transpose into As[k][m]) ----
        {
            const int r  = tid >> 2;           // 0..63
            const int c4 = (tid & 3) * 4;      // 0,4,8,12
#pragma unroll
            for (int it = 0; it < 2; it++) {
                const int m = r + it * 64;
                float4 v = *(const float4*)(A + (long long)(m0 + m) * K + k0 + c4);
                As[c4 + 0][m] = v.x; As[c4 + 1][m] = v.y;
                As[c4 + 2][m] = v.z; As[c4 + 3][m] = v.w;
            }
        }
        // ---- load B tile into Bs[k][n] ----
        if (BT) {
            const int r  = tid >> 2;
            const int c4 = (tid & 3) * 4;
#pragma unroll
            for (int it = 0; it < 2; it++) {
                const int n = r + it * 64;
                float4 v = *(const float4*)(B + (long long)(n0 + n) * K + k0 + c4);
                Bs[c4 + 0][n] = v.x; Bs[c4 + 1][n] = v.y;
                Bs[c4 + 2][n] = v.z; Bs[c4 + 3][n] = v.w;
            }
        } else {
            const int kk = tid >> 5;           // 0..7
            const int n4 = (tid & 31) * 4;     // 0..124
#pragma unroll
            for (int it = 0; it < 2; it++) {
                const int k = kk + it * 8;
                *(float4*)&Bs[k][n4] =
                    *(const float4*)(B + (long long)(k0 + k) * N + n0 + n4);
            }
        }
        __syncthreads();

#pragma unroll
        for (int k = 0; k < BK; k++) {
            float a[8], b[8];
            *(float4*)&a[0] = *(const float4*)&As[k][ty * 4];
            *(float4*)&a[4] = *(const float4*)&As[k][64 + ty * 4];
            *(float4*)&b[0] = *(const float4*)&Bs[k][tx * 4];
            *(float4*)&b[4] = *(const float4*)&Bs[k][64 + tx * 4];
#pragma unroll
            for (int i = 0; i < 8; i++)
#pragma unroll
                for (int j = 0; j < 8; j++)
                    acc[i][j] += a[i] * b[j];
        }
        __syncthreads();
    }

    // ---- epilogue ----
#pragma unroll
    for (int i = 0; i < 8; i++) {
        const int m = m0 + ((i < 4) ? (ty * 4 + i) : (64 + ty * 4 + (i - 4)));
#pragma unroll
        for (int jq = 0; jq < 2; jq++) {
            const int n = n0 + tx * 4 + jq * 64;
            const long long off = (long long)m * N + n;
            float r0 = acc[i][jq * 4 + 0];
            float r1 = acc[i][jq * 4 + 1];
            float r2 = acc[i][jq * 4 + 2];
            float r3 = acc[i][jq * 4 + 3];
            if (EPI == 1) {
                r0 = siluf(clip5(r0)); r1 = siluf(clip5(r1));
                r2 = siluf(clip5(r2)); r3 = siluf(clip5(r3));
            } else if (EPI == 2) {
                float4 e = *(const float4*)(Ex + off);
                r0 *= siluf(e.x); r1 *= siluf(e.y);
                r2 *= siluf(e.z); r3 *= siluf(e.w);
            } else if (EPI == 3) {
                float4 e = *(const float4*)(Ex + off);
                r0 = e.x + 0.1f * r0; r1 = e.y + 0.1f * r1;
                r2 = e.z + 0.1f * r2; r3 = e.w + 0.1f * r3;
            }
            float4 w = make_float4(r0, r1, r2, r3);
            *(float4*)(C + off) = w;
        }
    }
}

// ---------------- LayerNorm over rows of length 128 ------------------------
// out[row, c] = (v - mean) * rsqrt(var + 1e-5) * g[c] + b[c]
// one block (128 threads) per row; in-place safe.
__global__ void ln_kernel(const float* __restrict__ in,
                          const float* __restrict__ g,
                          const float* __restrict__ b,
                          float* __restrict__ out)
{
    const int row = blockIdx.x;
    const int c = threadIdx.x;
    const float v = in[(long long)row * Aa + c];
    float s = v, s2 = v * v;
#pragma unroll
    for (int o = 16; o > 0; o >>= 1) {
        s  += __shfl_xor_sync(0xffffffffu, s,  o);
        s2 += __shfl_xor_sync(0xffffffffu, s2, o);
    }
    __shared__ float ps[4], ps2[4];
    const int w = c >> 5, l = c & 31;
    if (l == 0) { ps[w] = s; ps2[w] = s2; }
    __syncthreads();
    const float ts  = ps[0] + ps[1] + ps[2] + ps[3];
    const float ts2 = ps2[0] + ps2[1] + ps2[2] + ps2[3];
    const float m   = ts * (1.0f / 128.0f);
    const float var = ts2 * (1.0f / 128.0f) - m * m;
    out[(long long)row * Aa + c] = (v - m) * rsqrtf(var + 1e-5f) * g[c] + b[c];
}

// ---------------- expert select + a = ln(pre @ w_exp[e]^T) -----------------
// One block (128 threads) per token. Masked-overwrite semantics: the LAST
// expert i with weight > 0 wins; if none, row is zero (=> contributes 0).
__global__ void expert_kernel(const float* __restrict__ pre,
                              const float* __restrict__ ew,
                              const float* __restrict__ w_exp,
                              const float* __restrict__ eg,
                              const float* __restrict__ eb,
                              float* __restrict__ abuf)
{
    const int token = blockIdx.x;
    const int c = threadIdx.x;

    int e = -1;
#pragma unroll
    for (int i = 0; i < 8; i++)
        if (ew[(long long)token * 8 + i] > 0.0f) e = i;

    if (e < 0) { abuf[(long long)token * Aa + c] = 0.0f; return; }

    __shared__ float sp[Aa];
    sp[c] = pre[(long long)token * Aa + c];
    __syncthreads();

    const float* wrow = w_exp + ((long long)e * Aa + c) * Aa;
    float t = 0.0f;
#pragma unroll 8
    for (int a = 0; a < Aa; a++) t += sp[a] * wrow[a];

    float s = t, s2 = t * t;
#pragma unroll
    for (int o = 16; o > 0; o >>= 1) {
        s  += __shfl_xor_sync(0xffffffffu, s,  o);
        s2 += __shfl_xor_sync(0xffffffffu, s2, o);
    }
    __shared__ float ps[4], ps2[4];
    const int w = c >> 5, l = c & 31;
    if (l == 0) { ps[w] = s; ps2[w] = s2; }
    __syncthreads();
    const float ts  = ps[0] + ps[1] + ps[2] + ps[3];
    const float ts2 = ps2[0] + ps2[1] + ps2[2] + ps2[3];
    const float m   = ts * (1.0f / 128.0f);
    const float var = ts2 * (1.0f / 128.0f) - m * m;
    abuf[(long long)token * Aa + c] =
        (t - m) * rsqrtf(var + 1e-5f) * eg[(long long)e * Aa + c] + eb[(long long)e * Aa + c];
}

// ---------------- launcher --------------------------------------------------
extern "C" void kernel_launch(void* const* d_in, const int* in_sizes, int n_in,
                              void* d_out, int out_size)
{
    const float* x       = (const float*)d_in[0];   // [B,S,D]
    const float* ew      = (const float*)d_in[1];   // [B,S,E]
    const float* w_up    = (const float*)d_in[2];   // [H,D]
    const float* w_gate  = (const float*)d_in[3];   // [H,D]
    const float* w_down  = (const float*)d_in[4];   // [D,H]
    const float* w_pre   = (const float*)d_in[5];   // [A,D]
    const float* w_post  = (const float*)d_in[6];   // [A,H]
    const float* an_g    = (const float*)d_in[7];   // [A]
    const float* an_b    = (const float*)d_in[8];   // [A]
    const float* w_aproj = (const float*)d_in[9];   // [H,A]
    const float* w_exp   = (const float*)d_in[10];  // [E,A,A]
    const float* eln_g   = (const float*)d_in[11];  // [E,A]
    const float* eln_b   = (const float*)d_in[12];  // [E,A]
    const float* w_eproj = (const float*)d_in[13];  // [H,A]
    const float* w_out   = (const float*)d_in[14];  // [D,H]
    float* out = (float*)d_out;                     // [B,S,D]

    float *gate, *hidden, *pre, *ain, *aout, *adapt, *abuf, *aw, *Wc;
    cudaGetSymbolAddress((void**)&gate,   g_gate);
    cudaGetSymbolAddress((void**)&hidden, g_hidden);
    cudaGetSymbolAddress((void**)&pre,    g_pre);
    cudaGetSymbolAddress((void**)&ain,    g_ain);
    cudaGetSymbolAddress((void**)&aout,   g_aout);
    cudaGetSymbolAddress((void**)&adapt,  g_adapt);
    cudaGetSymbolAddress((void**)&abuf,   g_abuf);
    cudaGetSymbolAddress((void**)&aw,     g_aw);
    cudaGetSymbolAddress((void**)&Wc,     g_W);

    const dim3 blk(256);

    // L1: gate = x @ w_gate^T                      [16384,2048]
    gemm_kernel<true, 0><<<dim3(Hh / BN, TOKENS / BM, 1), blk>>>(
        x, w_gate, nullptr, gate, TOKENS, Hh, Dd, 0, 0, 0);

    // L2: hidden = silu(gate) * (x @ w_up^T)       [16384,2048]
    gemm_kernel<true, 2><<<dim3(Hh / BN, TOKENS / BM, 1), blk>>>(
        x, w_up, gate, hidden, TOKENS, Hh, Dd, 0, 0, 0);

    // L3: pre = x @ w_pre^T                        [16384,128]
    gemm_kernel<true, 0><<<dim3(Aa / BN, TOKENS / BM, 1), blk>>>(
        x, w_pre, nullptr, pre, TOKENS, Aa, Dd, 0, 0, 0);

    // L4: adapt_in = ln(pre)
    ln_kernel<<<TOKENS, Aa>>>(pre, an_g, an_b, ain);

    // L5: aout = hidden @ w_post^T                 [16384,128]
    gemm_kernel<true, 0><<<dim3(Aa / BN, TOKENS / BM, 1), blk>>>(
        hidden, w_post, nullptr, aout, TOKENS, Aa, Hh, 0, 0, 0);

    // L6: adapt_out = ln(aout)  (in-place)
    ln_kernel<<<TOKENS, Aa>>>(aout, an_g, an_b, aout);

    // L7: aw[b] = silu(clip(adapt_in[b] @ adapt_out[b]^T))   [8,2048,2048]
    gemm_kernel<true, 1><<<dim3(Ss / BN, Ss / BM, Bb), blk>>>(
        ain, aout, nullptr, aw, Ss, Ss, Aa,
        (long long)Ss * Aa, (long long)Ss * Aa, (long long)Ss * Ss);

    // L8: adapt[b] = aw[b] @ adapt_in[b]           [8,2048,128]  (NN)
    gemm_kernel<false, 0><<<dim3(Aa / BN, Ss / BM, Bb), blk>>>(
        aw, ain, nullptr, adapt, Ss, Aa, Ss,
        (long long)Ss * Ss, (long long)Ss * Aa, (long long)Ss * Aa);

    // L9: hidden += 0.1 * adapt @ w_aproj^T        [16384,2048]
    gemm_kernel<true, 3><<<dim3(Hh / BN, TOKENS / BM, 1), blk>>>(
        adapt, w_aproj, hidden, hidden, TOKENS, Hh, Aa, 0, 0, 0);

    // L10: out = hidden @ w_down^T                 [16384,1024]
    gemm_kernel<true, 0><<<dim3(Dd / BN, TOKENS / BM, 1), blk>>>(
        hidden, w_down, nullptr, out, TOKENS, Dd, Hh, 0, 0, 0);

    // L11: Wc = w_out @ w_eproj                    [1024,128]  (NN)
    gemm_kernel<false, 0><<<dim3(Aa / BN, Dd / BM, 1), blk>>>(
        w_out, w_eproj, nullptr, Wc, Dd, Aa, Hh, 0, 0, 0);

    // L12: per-token expert select + a = ln(pre @ w_exp[e]^T)
    expert_kernel<<<TOKENS, Aa>>>(pre, ew, w_exp, eln_g, eln_b, abuf);

    // L13: out += 0.1 * abuf @ Wc^T                [16384,1024]
    gemm_kernel<true, 3><<<dim3(Dd / BN, TOKENS / BM, 1), blk>>>(
        abuf, Wc, out, out, TOKENS, Dd, Aa, 0, 0, 0);
}

// round 5
// speedup vs baseline: 1.3295x; 1.3295x over previous
#include <cuda_runtime.h>
#include <cstdint>
#include <math.h>

#define TOKENS 16384   // B*S
#define Dd 1024
#define Hh 2048
#define Aa 128
#define Ss 2048
#define Bb 8

// ---------------- scratch (device globals; no allocation allowed) ----------
__device__ float g_gate  [(size_t)TOKENS * Hh];
__device__ float g_hidden[(size_t)TOKENS * Hh];
__device__ float g_pre   [(size_t)TOKENS * Aa];
__device__ float g_ain   [(size_t)TOKENS * Aa];
__device__ float g_ainT  [(size_t)TOKENS * Aa];   // per-batch [Aa][Ss]
__device__ float g_aout  [(size_t)TOKENS * Aa];
__device__ float g_adapt [(size_t)TOKENS * Aa];
__device__ float g_abuf  [(size_t)TOKENS * Aa];
__device__ float g_aw    [(size_t)Bb * Ss * Ss];
__device__ float g_W     [(size_t)Dd * Aa];       // w_out @ w_eproj
// tf32-rounded copies of inputs
__device__ float g_xr     [(size_t)TOKENS * Dd];
__device__ float g_wupr   [(size_t)Hh * Dd];
__device__ float g_wgater [(size_t)Hh * Dd];
__device__ float g_wdownr [(size_t)Dd * Hh];
__device__ float g_wprer  [(size_t)Aa * Dd];
__device__ float g_wpostr [(size_t)Aa * Hh];
__device__ float g_waprojr[(size_t)Hh * Aa];
__device__ float g_weprojT[(size_t)Aa * Hh];      // rounded + transposed
__device__ float g_woutr  [(size_t)Dd * Hh];

// ---------------- helpers --------------------------------------------------
__device__ __forceinline__ float siluf(float x) { return x / (1.0f + __expf(-x)); }
__device__ __forceinline__ float clip5(float x) { return fminf(fmaxf(x, -5.0f), 5.0f); }

// round fp32 -> nearest tf32 (RNE), stored as fp32 with low 13 bits zero
__device__ __forceinline__ float rn_tf32(float f) {
    unsigned u = __float_as_uint(f);
    u = (u + 0xFFFu + ((u >> 13) & 1u)) & 0xFFFFE000u;
    return __uint_as_float(u);
}

__device__ __forceinline__ unsigned smem_u32(const void* p) {
    unsigned a;
    asm("{ .reg .u64 t; cvta.to.shared.u64 t, %1; cvt.u32.u64 %0, t; }"
        : "=r"(a) : "l"(p));
    return a;
}

// ---------------- tf32 mma.sync GEMM (NT): C = A[M,K] @ B[N,K]^T -----------
// Tile 128x128, BK=16, 256 threads, cp.async double buffer.
// EPI 0: acc | 1: silu(clip(acc)) | 2: silu(E)*acc | 3: E + 0.1*acc
// RND: round output to tf32 grid (for buffers feeding later MMAs)
template <int EPI, bool RND>
__global__ void __launch_bounds__(256)
tc_gemm(const float* __restrict__ Ag, const float* __restrict__ Bg,
        const float* __restrict__ Eg, float* __restrict__ Cg,
        int K, int lda, int ldb, int ldc,
        long long sA, long long sB, long long sC)
{
    __shared__ float sAt[2][128][20];   // pad 16->20: conflict-free fragments
    __shared__ float sBt[2][128][20];

    const int tid  = threadIdx.x;
    const int wid  = tid >> 5, lane = tid & 31;
    const int g    = lane >> 2, t = lane & 3;
    const int wm   = wid >> 2, wn = wid & 3;          // 2 x 4 warp grid
    const int m0   = blockIdx.y * 128, n0 = blockIdx.x * 128;

    const float* A = Ag + (long long)blockIdx.z * sA;
    const float* B = Bg + (long long)blockIdx.z * sB;
    float*       C = Cg + (long long)blockIdx.z * sC;
    const float* E = (EPI == 2 || EPI == 3) ? (Eg + (long long)blockIdx.z * sC) : nullptr;

    float c[4][4][4];
#pragma unroll
    for (int i = 0; i < 4; i++)
#pragma unroll
        for (int j = 0; j < 4; j++)
#pragma unroll
            for (int r = 0; r < 4; r++) c[i][j][r] = 0.0f;

    const int NC = K >> 4;

    auto fill = [&](int s, int ck) {
        const int k0 = ck << 4;
#pragma unroll
        for (int i = 0; i < 2; i++) {
            const int slot = tid + i * 256;           // 512 float4 slots
            const int row = slot >> 2, f4 = slot & 3;
            unsigned dst = smem_u32(&sAt[s][row][f4 * 4]);
            const float* src = A + (long long)(m0 + row) * lda + k0 + f4 * 4;
            asm volatile("cp.async.ca.shared.global [%0], [%1], 16;"
                         :: "r"(dst), "l"(src));
        }
#pragma unroll
        for (int i = 0; i < 2; i++) {
            const int slot = tid + i * 256;
            const int row = slot >> 2, f4 = slot & 3;
            unsigned dst = smem_u32(&sBt[s][row][f4 * 4]);
            const float* src = B + (long long)(n0 + row) * ldb + k0 + f4 * 4;
            asm volatile("cp.async.ca.shared.global [%0], [%1], 16;"
                         :: "r"(dst), "l"(src));
        }
    };

    auto compute = [&](int s) {
#pragma unroll
        for (int ks = 0; ks < 16; ks += 8) {
            unsigned a[4][4], b[4][2];
#pragma unroll
            for (int mt = 0; mt < 4; mt++) {
                const int r = wm * 64 + mt * 16;
                a[mt][0] = __float_as_uint(sAt[s][r + g    ][ks + t    ]);
                a[mt][1] = __float_as_uint(sAt[s][r + g + 8][ks + t    ]);
                a[mt][2] = __float_as_uint(sAt[s][r + g    ][ks + t + 4]);
                a[mt][3] = __float_as_uint(sAt[s][r + g + 8][ks + t + 4]);
            }
#pragma unroll
            for (int nt = 0; nt < 4; nt++) {
                const int n = wn * 32 + nt * 8 + g;
                b[nt][0] = __float_as_uint(sBt[s][n][ks + t    ]);
                b[nt][1] = __float_as_uint(sBt[s][n][ks + t + 4]);
            }
#pragma unroll
            for (int mt = 0; mt < 4; mt++)
#pragma unroll
                for (int nt = 0; nt < 4; nt++)
                    asm volatile(
                        "mma.sync.aligned.m16n8k8.row.col.f32.tf32.tf32.f32 "
                        "{%0,%1,%2,%3}, {%4,%5,%6,%7}, {%8,%9}, {%0,%1,%2,%3};"
                        : "+f"(c[mt][nt][0]), "+f"(c[mt][nt][1]),
                          "+f"(c[mt][nt][2]), "+f"(c[mt][nt][3])
                        : "r"(a[mt][0]), "r"(a[mt][1]), "r"(a[mt][2]), "r"(a[mt][3]),
                          "r"(b[nt][0]), "r"(b[nt][1]));
        }
    };

    // prologue
    fill(0, 0);
    asm volatile("cp.async.commit_group;" ::: "memory");

    for (int ck = 0; ck < NC; ck++) {
        if (ck + 1 < NC) {
            fill((ck + 1) & 1, ck + 1);
            asm volatile("cp.async.commit_group;" ::: "memory");
            asm volatile("cp.async.wait_group 1;" ::: "memory");
        } else {
            asm volatile("cp.async.wait_group 0;" ::: "memory");
        }
        __syncthreads();
        compute(ck & 1);
        __syncthreads();
    }

    // ---- epilogue: direct stores (float2 = full 32B sectors per 8 lanes) ----
#pragma unroll
    for (int mt = 0; mt < 4; mt++) {
#pragma unroll
        for (int half = 0; half < 2; half++) {
            const int r = m0 + wm * 64 + mt * 16 + g + half * 8;
#pragma unroll
            for (int nt = 0; nt < 4; nt++) {
                const int col = n0 + wn * 32 + nt * 8 + 2 * t;
                const long long off = (long long)r * ldc + col;
                float v0 = c[mt][nt][half * 2 + 0];
                float v1 = c[mt][nt][half * 2 + 1];
                if (EPI == 1) {
                    v0 = siluf(clip5(v0)); v1 = siluf(clip5(v1));
                } else if (EPI == 2) {
                    float2 e = *(const float2*)(E + off);
                    v0 *= siluf(e.x); v1 *= siluf(e.y);
                } else if (EPI == 3) {
                    float2 e = *(const float2*)(E + off);
                    v0 = e.x + 0.1f * v0; v1 = e.y + 0.1f * v1;
                }
                if (RND) { v0 = rn_tf32(v0); v1 = rn_tf32(v1); }
                *(float2*)(C + off) = make_float2(v0, v1);
            }
        }
    }
}

// ---------------- elementwise tf32 rounding --------------------------------
__global__ void round_kernel(const float* __restrict__ in, float* __restrict__ out, int n4)
{
    int i = blockIdx.x * blockDim.x + threadIdx.x;
    if (i < n4) {
        float4 v = ((const float4*)in)[i];
        v.x = rn_tf32(v.x); v.y = rn_tf32(v.y);
        v.z = rn_tf32(v.z); v.w = rn_tf32(v.w);
        ((float4*)out)[i] = v;
    }
}

// ---------------- tiled transpose (with tf32 rounding): out[C][R]=in[R][C] --
__global__ void transpose_kernel(const float* __restrict__ in, float* __restrict__ out,
                                 int R, int C, long long sIn, long long sOut)
{
    __shared__ float tile[32][33];
    const float* ip = in + (long long)blockIdx.z * sIn;
    float*       op = out + (long long)blockIdx.z * sOut;
    const int c0 = blockIdx.x * 32, r0 = blockIdx.y * 32;
    const int tx = threadIdx.x, ty = threadIdx.y;
#pragma unroll
    for (int j = 0; j < 32; j += 8)
        tile[ty + j][tx] = rn_tf32(ip[(long long)(r0 + ty + j) * C + c0 + tx]);
    __syncthreads();
#pragma unroll
    for (int j = 0; j < 32; j += 8)
        op[(long long)(c0 + ty + j) * R + r0 + tx] = tile[tx][ty + j];
}

// ---------------- LayerNorm over rows of length 128 (tf32-rounded out) -----
__global__ void ln_kernel(const float* __restrict__ in,
                          const float* __restrict__ g,
                          const float* __restrict__ b,
                          float* __restrict__ out)
{
    const int row = blockIdx.x;
    const int c = threadIdx.x;
    const float v = in[(long long)row * Aa + c];
    float s = v, s2 = v * v;
#pragma unroll
    for (int o = 16; o > 0; o >>= 1) {
        s  += __shfl_xor_sync(0xffffffffu, s,  o);
        s2 += __shfl_xor_sync(0xffffffffu, s2, o);
    }
    __shared__ float ps[4], ps2[4];
    const int w = c >> 5, l = c & 31;
    if (l == 0) { ps[w] = s; ps2[w] = s2; }
    __syncthreads();
    const float ts  = ps[0] + ps[1] + ps[2] + ps[3];
    const float ts2 = ps2[0] + ps2[1] + ps2[2] + ps2[3];
    const float m   = ts * (1.0f / 128.0f);
    const float var = ts2 * (1.0f / 128.0f) - m * m;
    out[(long long)row * Aa + c] =
        rn_tf32((v - m) * rsqrtf(var + 1e-5f) * g[c] + b[c]);
}

// ---------------- expert select + a = ln(pre @ w_exp[e]^T) -----------------
__global__ void expert_kernel(const float* __restrict__ pre,
                              const float* __restrict__ ew,
                              const float* __restrict__ w_exp,
                              const float* __restrict__ eg,
                              const float* __restrict__ eb,
                              float* __restrict__ abuf)
{
    const int token = blockIdx.x;
    const int c = threadIdx.x;

    int e = -1;
#pragma unroll
    for (int i = 0; i < 8; i++)
        if (ew[(long long)token * 8 + i] > 0.0f) e = i;

    if (e < 0) { abuf[(long long)token * Aa + c] = 0.0f; return; }

    __shared__ float sp[Aa];
    sp[c] = pre[(long long)token * Aa + c];
    __syncthreads();

    const float* wrow = w_exp + ((long long)e * Aa + c) * Aa;
    float tacc = 0.0f;
#pragma unroll 8
    for (int a = 0; a < Aa; a++) tacc += sp[a] * wrow[a];

    float s = tacc, s2 = tacc * tacc;
#pragma unroll
    for (int o = 16; o > 0; o >>= 1) {
        s  += __shfl_xor_sync(0xffffffffu, s,  o);
        s2 += __shfl_xor_sync(0xffffffffu, s2, o);
    }
    __shared__ float ps[4], ps2[4];
    const int w = c >> 5, l = c & 31;
    if (l == 0) { ps[w] = s; ps2[w] = s2; }
    __syncthreads();
    const float ts  = ps[0] + ps[1] + ps[2] + ps[3];
    const float ts2 = ps2[0] + ps2[1] + ps2[2] + ps2[3];
    const float m   = ts * (1.0f / 128.0f);
    const float var = ts2 * (1.0f / 128.0f) - m * m;
    abuf[(long long)token * Aa + c] = rn_tf32(
        (tacc - m) * rsqrtf(var + 1e-5f) * eg[(long long)e * Aa + c]
        + eb[(long long)e * Aa + c]);
}

// ---------------- launcher --------------------------------------------------
extern "C" void kernel_launch(void* const* d_in, const int* in_sizes, int n_in,
                              void* d_out, int out_size)
{
    const float* x       = (const float*)d_in[0];
    const float* ew      = (const float*)d_in[1];
    const float* w_up    = (const float*)d_in[2];
    const float* w_gate  = (const float*)d_in[3];
    const float* w_down  = (const float*)d_in[4];
    const float* w_pre   = (const float*)d_in[5];
    const float* w_post  = (const float*)d_in[6];
    const float* an_g    = (const float*)d_in[7];
    const float* an_b    = (const float*)d_in[8];
    const float* w_aproj = (const float*)d_in[9];
    const float* w_exp   = (const float*)d_in[10];
    const float* eln_g   = (const float*)d_in[11];
    const float* eln_b   = (const float*)d_in[12];
    const float* w_eproj = (const float*)d_in[13];
    const float* w_out   = (const float*)d_in[14];
    float* out = (float*)d_out;

    float *gate, *hidden, *pre, *ain, *ainT, *aout, *adapt, *abuf, *aw, *Wc;
    float *xr, *wupr, *wgater, *wdownr, *wprer, *wpostr, *waprojr, *weprojT, *woutr;
    cudaGetSymbolAddress((void**)&gate,    g_gate);
    cudaGetSymbolAddress((void**)&hidden,  g_hidden);
    cudaGetSymbolAddress((void**)&pre,     g_pre);
    cudaGetSymbolAddress((void**)&ain,     g_ain);
    cudaGetSymbolAddress((void**)&ainT,    g_ainT);
    cudaGetSymbolAddress((void**)&aout,    g_aout);
    cudaGetSymbolAddress((void**)&adapt,   g_adapt);
    cudaGetSymbolAddress((void**)&abuf,    g_abuf);
    cudaGetSymbolAddress((void**)&aw,      g_aw);
    cudaGetSymbolAddress((void**)&Wc,      g_W);
    cudaGetSymbolAddress((void**)&xr,      g_xr);
    cudaGetSymbolAddress((void**)&wupr,    g_wupr);
    cudaGetSymbolAddress((void**)&wgater,  g_wgater);
    cudaGetSymbolAddress((void**)&wdownr,  g_wdownr);
    cudaGetSymbolAddress((void**)&wprer,   g_wprer);
    cudaGetSymbolAddress((void**)&wpostr,  g_wpostr);
    cudaGetSymbolAddress((void**)&waprojr, g_waprojr);
    cudaGetSymbolAddress((void**)&weprojT, g_weprojT);
    cudaGetSymbolAddress((void**)&woutr,   g_woutr);

    const dim3 blk(256);

    // ---- round inputs to tf32 grid ----
    auto rnd = [&](const float* in, float* o, long long n) {
        int n4 = (int)(n / 4);
        round_kernel<<<(n4 + 255) / 256, 256>>>(in, o, n4);
    };
    rnd(x,       xr,      (long long)TOKENS * Dd);
    rnd(w_up,    wupr,    (long long)Hh * Dd);
    rnd(w_gate,  wgater,  (long long)Hh * Dd);
    rnd(w_down,  wdownr,  (long long)Dd * Hh);
    rnd(w_pre,   wprer,   (long long)Aa * Dd);
    rnd(w_post,  wpostr,  (long long)Aa * Hh);
    rnd(w_aproj, waprojr, (long long)Hh * Aa);
    rnd(w_out,   woutr,   (long long)Dd * Hh);

    // w_eproj: round + transpose -> [Aa][Hh]
    transpose_kernel<<<dim3(Aa / 32, Hh / 32, 1), dim3(32, 8)>>>(
        w_eproj, weprojT, Hh, Aa, 0, 0);

    // L11: Wc = w_out @ w_eproj  [Dd,Aa]  (NT vs weprojT), rounded
    tc_gemm<0, true><<<dim3(Aa / 128, Dd / 128, 1), blk>>>(
        woutr, weprojT, nullptr, Wc, Hh, Hh, Hh, Aa, 0, 0, 0);

    // L1: gate = x @ w_gate^T     [16384,2048]
    tc_gemm<0, false><<<dim3(Hh / 128, TOKENS / 128, 1), blk>>>(
        xr, wgater, nullptr, gate, Dd, Dd, Dd, Hh, 0, 0, 0);

    // L2: hidden = silu(gate) * (x @ w_up^T), rounded
    tc_gemm<2, true><<<dim3(Hh / 128, TOKENS / 128, 1), blk>>>(
        xr, wupr, gate, hidden, Dd, Dd, Dd, Hh, 0, 0, 0);

    // L3: pre = x @ w_pre^T       [16384,128]  (consumed fp32 by ln/expert)
    tc_gemm<0, false><<<dim3(1, TOKENS / 128, 1), blk>>>(
        xr, wprer, nullptr, pre, Dd, Dd, Dd, Aa, 0, 0, 0);

    // L4: adapt_in = ln(pre), rounded
    ln_kernel<<<TOKENS, Aa>>>(pre, an_g, an_b, ain);

    // L5: aout = hidden @ w_post^T  [16384,128]
    tc_gemm<0, false><<<dim3(1, TOKENS / 128, 1), blk>>>(
        hidden, wpostr, nullptr, aout, Hh, Hh, Hh, Aa, 0, 0, 0);

    // L6: adapt_out = ln(aout) in-place, rounded
    ln_kernel<<<TOKENS, Aa>>>(aout, an_g, an_b, aout);

    // L7: aw[b] = silu(clip(ain[b] @ aout[b]^T))  [8,2048,2048], rounded
    tc_gemm<1, true><<<dim3(Ss / 128, Ss / 128, Bb), blk>>>(
        ain, aout, nullptr, aw, Aa, Aa, Aa, Ss,
        (long long)Ss * Aa, (long long)Ss * Aa, (long long)Ss * Ss);

    // transpose ain per batch: [Ss,Aa] -> [Aa,Ss]
    transpose_kernel<<<dim3(Aa / 32, Ss / 32, Bb), dim3(32, 8)>>>(
        ain, ainT, Ss, Aa, (long long)Ss * Aa, (long long)Aa * Ss);

    // L8: adapt[b] = aw[b] @ ain[b]  [8,2048,128]  (NT vs ainT), rounded
    tc_gemm<0, true><<<dim3(1, Ss / 128, Bb), blk>>>(
        aw, ainT, nullptr, adapt, Ss, Ss, Ss, Aa,
        (long long)Ss * Ss, (long long)Aa * Ss, (long long)Ss * Aa);

    // L9: hidden += 0.1 * adapt @ w_aproj^T, rounded
    tc_gemm<3, true><<<dim3(Hh / 128, TOKENS / 128, 1), blk>>>(
        adapt, waprojr, hidden, hidden, Aa, Aa, Aa, Hh, 0, 0, 0);

    // L10: out = hidden @ w_down^T  [16384,1024]  (fp32 out)
    tc_gemm<0, false><<<dim3(Dd / 128, TOKENS / 128, 1), blk>>>(
        hidden, wdownr, nullptr, out, Hh, Hh, Hh, Dd, 0, 0, 0);

    // L12: expert select + a = ln(pre @ w_exp[e]^T), rounded
    expert_kernel<<<TOKENS, Aa>>>(pre, ew, w_exp, eln_g, eln_b, abuf);

    // L13: out += 0.1 * abuf @ Wc^T  (fp32 out)
    tc_gemm<3, false><<<dim3(Dd / 128, TOKENS / 128, 1), blk>>>(
        abuf, Wc, out, out, Aa, Aa, Aa, Dd, 0, 0, 0);
}

// round 9
// speedup vs baseline: 3.2349x; 2.4331x over previous
#include <cuda_runtime.h>
#include <cuda_fp16.h>
#include <cstdint>
#include <math.h>

#define TOKENS 16384   // B*S
#define Dd 1024
#define Hh 2048
#define Aa 128
#define Ss 2048
#define Bb 8

// ---------------- scratch (device globals; no allocation allowed) ----------
__device__ float  g_gate  [(size_t)TOKENS * Hh];   // fp32 (silu input)
__device__ __half g_hidden[(size_t)TOKENS * Hh];
__device__ float  g_pre   [(size_t)TOKENS * Aa];   // fp32 (ln/expert input)
__device__ __half g_ain   [(size_t)TOKENS * Aa];
__device__ __half g_ainT  [(size_t)TOKENS * Aa];   // per-batch [Aa][Ss]
__device__ float  g_aoutf [(size_t)TOKENS * Aa];
__device__ __half g_aouth [(size_t)TOKENS * Aa];
__device__ __half g_adapt [(size_t)TOKENS * Aa];
__device__ __half g_abuf  [(size_t)TOKENS * Aa];
__device__ __half g_aw    [(size_t)Bb * Ss * Ss];  // 67 MB
__device__ __half g_W     [(size_t)Dd * Aa];       // w_out @ w_eproj
// fp16 copies of inputs
__device__ __half g_xh     [(size_t)TOKENS * Dd];
__device__ __half g_wuph   [(size_t)Hh * Dd];
__device__ __half g_wgateh [(size_t)Hh * Dd];
__device__ __half g_wdownh [(size_t)Dd * Hh];
__device__ __half g_wpreh  [(size_t)Aa * Dd];
__device__ __half g_wposth [(size_t)Aa * Hh];
__device__ __half g_waprojh[(size_t)Hh * Aa];
__device__ __half g_weprojT[(size_t)Aa * Hh];      // transposed
__device__ __half g_wouth  [(size_t)Dd * Hh];

// ---------------- helpers --------------------------------------------------
__device__ __forceinline__ float siluf(float x) { return x / (1.0f + __expf(-x)); }
__device__ __forceinline__ float clip5(float x) { return fminf(fmaxf(x, -5.0f), 5.0f); }

__device__ __forceinline__ unsigned smem_u32(const void* p) {
    unsigned a;
    asm("{ .reg .u64 t; cvta.to.shared.u64 t, %1; cvt.u32.u64 %0, t; }"
        : "=r"(a) : "l"(p));
    return a;
}

// ---------------- fp16 mma.sync GEMM (NT): C = A[M,K] @ B[N,K]^T -----------
// Tile 128x128, BK=32, 256 threads, cp.async double buffer, ldmatrix frags.
// EPI 0: acc | 1: silu(clip(acc)) | 2: silu(Ef)*acc | 3: Eh+0.1*acc | 4: Ef+0.1*acc
// OUTH: store __half, else float.
#define SROW 40   // padded row stride in halves (conflict-free ldmatrix)

template <int EPI, bool OUTH>
__global__ void __launch_bounds__(256)
tc_gemm(const __half* __restrict__ Ag, const __half* __restrict__ Bg,
        const void* __restrict__ Eg, void* __restrict__ Cg,
        int K, int lda, int ldb, int ldc,
        long long sA, long long sB, long long sC)
{
    __shared__ __half sAt[2][128][SROW];
    __shared__ __half sBt[2][128][SROW];

    const int tid  = threadIdx.x;
    const int wid  = tid >> 5, lane = tid & 31;
    const int g    = lane >> 2, t = lane & 3;
    const int wm   = wid >> 2, wn = wid & 3;          // 2 x 4 warp grid
    const int m0   = blockIdx.y * 128, n0 = blockIdx.x * 128;

    const __half* A = Ag + (long long)blockIdx.z * sA;
    const __half* B = Bg + (long long)blockIdx.z * sB;

    float c[4][4][4];
#pragma unroll
    for (int i = 0; i < 4; i++)
#pragma unroll
        for (int j = 0; j < 4; j++)
#pragma unroll
            for (int r = 0; r < 4; r++) c[i][j][r] = 0.0f;

    const int NC = K >> 5;

    auto fill = [&](int s, int ck) {
        const int k0 = ck << 5;
        // A: 128 rows x 32 halves = 512 x 16B; 256 thr x 2
#pragma unroll
        for (int i = 0; i < 2; i++) {
            const int slot = tid + i * 256;
            const int row = slot >> 2, j = slot & 3;
            unsigned dst = smem_u32(&sAt[s][row][j * 8]);
            const __half* src = A + (long long)(m0 + row) * lda + k0 + j * 8;
            asm volatile("cp.async.ca.shared.global [%0], [%1], 16;"
                         :: "r"(dst), "l"(src));
        }
#pragma unroll
        for (int i = 0; i < 2; i++) {
            const int slot = tid + i * 256;
            const int row = slot >> 2, j = slot & 3;
            unsigned dst = smem_u32(&sBt[s][row][j * 8]);
            const __half* src = B + (long long)(n0 + row) * ldb + k0 + j * 8;
            asm volatile("cp.async.ca.shared.global [%0], [%1], 16;"
                         :: "r"(dst), "l"(src));
        }
    };

    auto compute = [&](int s) {
        const unsigned baseA = smem_u32(&sAt[s][0][0]);
        const unsigned baseB = smem_u32(&sBt[s][0][0]);
#pragma unroll
        for (int ks = 0; ks < 2; ks++) {
            unsigned a[4][4], b[2][4];
#pragma unroll
            for (int mt = 0; mt < 4; mt++) {
                const int row = wm * 64 + mt * 16 + ((lane >> 3) & 1) * 8 + (lane & 7);
                const int kc  = ks * 16 + ((lane >> 4) & 1) * 8;
                unsigned addr = baseA + (unsigned)(row * SROW + kc) * 2u;
                asm volatile("ldmatrix.sync.aligned.m8n8.x4.shared.b16 "
                             "{%0,%1,%2,%3}, [%4];"
                             : "=r"(a[mt][0]), "=r"(a[mt][1]),
                               "=r"(a[mt][2]), "=r"(a[mt][3])
                             : "r"(addr));
            }
#pragma unroll
            for (int p = 0; p < 2; p++) {
                const int row = wn * 32 + p * 16 + ((lane >> 4) & 1) * 8 + (lane & 7);
                const int kc  = ks * 16 + ((lane >> 3) & 1) * 8;
                unsigned addr = baseB + (unsigned)(row * SROW + kc) * 2u;
                asm volatile("ldmatrix.sync.aligned.m8n8.x4.shared.b16 "
                             "{%0,%1,%2,%3}, [%4];"
                             : "=r"(b[p][0]), "=r"(b[p][1]),
                               "=r"(b[p][2]), "=r"(b[p][3])
                             : "r"(addr));
            }
#pragma unroll
            for (int mt = 0; mt < 4; mt++)
#pragma unroll
                for (int nt = 0; nt < 4; nt++) {
                    const int p = nt >> 1, q = (nt & 1) * 2;
                    asm volatile(
                        "mma.sync.aligned.m16n8k16.row.col.f32.f16.f16.f32 "
                        "{%0,%1,%2,%3}, {%4,%5,%6,%7}, {%8,%9}, {%0,%1,%2,%3};"
                        : "+f"(c[mt][nt][0]), "+f"(c[mt][nt][1]),
                          "+f"(c[mt][nt][2]), "+f"(c[mt][nt][3])
                        : "r"(a[mt][0]), "r"(a[mt][1]), "r"(a[mt][2]), "r"(a[mt][3]),
                          "r"(b[p][q]), "r"(b[p][q + 1]));
                }
        }
    };

    fill(0, 0);
    asm volatile("cp.async.commit_group;" ::: "memory");

    for (int ck = 0; ck < NC; ck++) {
        if (ck + 1 < NC) {
            fill((ck + 1) & 1, ck + 1);
            asm volatile("cp.async.commit_group;" ::: "memory");
            asm volatile("cp.async.wait_group 1;" ::: "memory");
        } else {
            asm volatile("cp.async.wait_group 0;" ::: "memory");
        }
        __syncthreads();
        compute(ck & 1);
        __syncthreads();
    }

    // ---- epilogue ----
#pragma unroll
    for (int mt = 0; mt < 4; mt++) {
#pragma unroll
        for (int hf = 0; hf < 2; hf++) {
            const int r = m0 + wm * 64 + mt * 16 + g + hf * 8;
#pragma unroll
            for (int nt = 0; nt < 4; nt++) {
                const int col = n0 + wn * 32 + nt * 8 + 2 * t;
                const long long off = (long long)r * ldc + col
                                      + (long long)blockIdx.z * sC;
                float v0 = c[mt][nt][hf * 2 + 0];
                float v1 = c[mt][nt][hf * 2 + 1];
                if (EPI == 1) {
                    v0 = siluf(clip5(v0)); v1 = siluf(clip5(v1));
                } else if (EPI == 2) {
                    float2 e = *(const float2*)((const float*)Eg + off);
                    v0 *= siluf(e.x); v1 *= siluf(e.y);
                } else if (EPI == 3) {
                    __half2 e = *(const __half2*)((const __half*)Eg + off);
                    v0 = __half2float(e.x) + 0.1f * v0;
                    v1 = __half2float(e.y) + 0.1f * v1;
                } else if (EPI == 4) {
                    float2 e = *(const float2*)((const float*)Eg + off);
                    v0 = e.x + 0.1f * v0; v1 = e.y + 0.1f * v1;
                }
                if (OUTH) {
                    *(__half2*)((__half*)Cg + off) =
                        __floats2half2_rn(v0, v1);
                } else {
                    *(float2*)((float*)Cg + off) = make_float2(v0, v1);
                }
            }
        }
    }
}

// ---------------- fp32 -> fp16 conversion ----------------------------------
__global__ void cvt_h(const float* __restrict__ in, __half* __restrict__ out, int n4)
{
    int i = blockIdx.x * blockDim.x + threadIdx.x;
    if (i < n4) {
        float4 v = ((const float4*)in)[i];
        __half2 h0 = __floats2half2_rn(v.x, v.y);
        __half2 h1 = __floats2half2_rn(v.z, v.w);
        ((__half2*)out)[2 * i] = h0;
        ((__half2*)out)[2 * i + 1] = h1;
    }
}

// ---------------- transposes ------------------------------------------------
__global__ void transpose_f2h(const float* __restrict__ in, __half* __restrict__ out,
                              int R, int C)
{
    __shared__ __half tile[32][33];
    const int c0 = blockIdx.x * 32, r0 = blockIdx.y * 32;
    const int tx = threadIdx.x, ty = threadIdx.y;
#pragma unroll
    for (int j = 0; j < 32; j += 8)
        tile[ty + j][tx] = __float2half_rn(in[(long long)(r0 + ty + j) * C + c0 + tx]);
    __syncthreads();
#pragma unroll
    for (int j = 0; j < 32; j += 8)
        out[(long long)(c0 + ty + j) * R + r0 + tx] = tile[tx][ty + j];
}

__global__ void transpose_h(const __half* __restrict__ in, __half* __restrict__ out,
                            int R, int C, long long sIn, long long sOut)
{
    __shared__ __half tile[32][33];
    const __half* ip = in + (long long)blockIdx.z * sIn;
    __half*       op = out + (long long)blockIdx.z * sOut;
    const int c0 = blockIdx.x * 32, r0 = blockIdx.y * 32;
    const int tx = threadIdx.x, ty = threadIdx.y;
#pragma unroll
    for (int j = 0; j < 32; j += 8)
        tile[ty + j][tx] = ip[(long long)(r0 + ty + j) * C + c0 + tx];
    __syncthreads();
#pragma unroll
    for (int j = 0; j < 32; j += 8)
        op[(long long)(c0 + ty + j) * R + r0 + tx] = tile[tx][ty + j];
}

// ---------------- LayerNorm over rows of length 128 (half out) -------------
__global__ void ln_kernel(const float* __restrict__ in,
                          const float* __restrict__ g,
                          const float* __restrict__ b,
                          __half* __restrict__ out)
{
    const int row = blockIdx.x;
    const int c = threadIdx.x;
    const float v = in[(long long)row * Aa + c];
    float s = v, s2 = v * v;
#pragma unroll
    for (int o = 16; o > 0; o >>= 1) {
        s  += __shfl_xor_sync(0xffffffffu, s,  o);
        s2 += __shfl_xor_sync(0xffffffffu, s2, o);
    }
    __shared__ float ps[4], ps2[4];
    const int w = c >> 5, l = c & 31;
    if (l == 0) { ps[w] = s; ps2[w] = s2; }
    __syncthreads();
    const float ts  = ps[0] + ps[1] + ps[2] + ps[3];
    const float ts2 = ps2[0] + ps2[1] + ps2[2] + ps2[3];
    const float m   = ts * (1.0f / 128.0f);
    const float var = ts2 * (1.0f / 128.0f) - m * m;
    out[(long long)row * Aa + c] =
        __float2half_rn((v - m) * rsqrtf(var + 1e-5f) * g[c] + b[c]);
}

// ---------------- expert select + a = ln(pre @ w_exp[e]^T) -----------------
__global__ void expert_kernel(const float* __restrict__ pre,
                              const float* __restrict__ ew,
                              const float* __restrict__ w_exp,
                              const float* __restrict__ eg,
                              const float* __restrict__ eb,
                              __half* __restrict__ abuf)
{
    const int token = blockIdx.x;
    const int c = threadIdx.x;

    int e = -1;
#pragma unroll
    for (int i = 0; i < 8; i++)
        if (ew[(long long)token * 8 + i] > 0.0f) e = i;

    if (e < 0) { abuf[(long long)token * Aa + c] = __float2half_rn(0.0f); return; }

    __shared__ float sp[Aa];
    sp[c] = pre[(long long)token * Aa + c];
    __syncthreads();

    const float* wrow = w_exp + ((long long)e * Aa + c) * Aa;
    float tacc = 0.0f;
#pragma unroll 8
    for (int a = 0; a < Aa; a++) tacc += sp[a] * wrow[a];

    float s = tacc, s2 = tacc * tacc;
#pragma unroll
    for (int o = 16; o > 0; o >>= 1) {
        s  += __shfl_xor_sync(0xffffffffu, s,  o);
        s2 += __shfl_xor_sync(0xffffffffu, s2, o);
    }
    __shared__ float ps[4], ps2[4];
    const int w = c >> 5, l = c & 31;
    if (l == 0) { ps[w] = s; ps2[w] = s2; }
    __syncthreads();
    const float ts  = ps[0] + ps[1] + ps[2] + ps[3];
    const float ts2 = ps2[0] + ps2[1] + ps2[2] + ps2[3];
    const float m   = ts * (1.0f / 128.0f);
    const float var = ts2 * (1.0f / 128.0f) - m * m;
    abuf[(long long)token * Aa + c] = __float2half_rn(
        (tacc - m) * rsqrtf(var + 1e-5f) * eg[(long long)e * Aa + c]
        + eb[(long long)e * Aa + c]);
}

// ---------------- launcher --------------------------------------------------
extern "C" void kernel_launch(void* const* d_in, const int* in_sizes, int n_in,
                              void* d_out, int out_size)
{
    const float* x       = (const float*)d_in[0];
    const float* ew      = (const float*)d_in[1];
    const float* w_up    = (const float*)d_in[2];
    const float* w_gate  = (const float*)d_in[3];
    const float* w_down  = (const float*)d_in[4];
    const float* w_pre   = (const float*)d_in[5];
    const float* w_post  = (const float*)d_in[6];
    const float* an_g    = (const float*)d_in[7];
    const float* an_b    = (const float*)d_in[8];
    const float* w_aproj = (const float*)d_in[9];
    const float* w_exp   = (const float*)d_in[10];
    const float* eln_g   = (const float*)d_in[11];
    const float* eln_b   = (const float*)d_in[12];
    const float* w_eproj = (const float*)d_in[13];
    const float* w_out   = (const float*)d_in[14];
    float* out = (float*)d_out;

    float *gate, *pre, *aoutf;
    __half *hidden, *ain, *ainT, *aouth, *adapt, *abuf, *aw, *Wc;
    __half *xh, *wuph, *wgateh, *wdownh, *wpreh, *wposth, *waprojh, *weprojT, *wouth;
    cudaGetSymbolAddress((void**)&gate,    g_gate);
    cudaGetSymbolAddress((void**)&hidden,  g_hidden);
    cudaGetSymbolAddress((void**)&pre,     g_pre);
    cudaGetSymbolAddress((void**)&ain,     g_ain);
    cudaGetSymbolAddress((void**)&ainT,    g_ainT);
    cudaGetSymbolAddress((void**)&aoutf,   g_aoutf);
    cudaGetSymbolAddress((void**)&aouth,   g_aouth);
    cudaGetSymbolAddress((void**)&adapt,   g_adapt);
    cudaGetSymbolAddress((void**)&abuf,    g_abuf);
    cudaGetSymbolAddress((void**)&aw,      g_aw);
    cudaGetSymbolAddress((void**)&Wc,      g_W);
    cudaGetSymbolAddress((void**)&xh,      g_xh);
    cudaGetSymbolAddress((void**)&wuph,    g_wuph);
    cudaGetSymbolAddress((void**)&wgateh,  g_wgateh);
    cudaGetSymbolAddress((void**)&wdownh,  g_wdownh);
    cudaGetSymbolAddress((void**)&wpreh,   g_wpreh);
    cudaGetSymbolAddress((void**)&wposth,  g_wposth);
    cudaGetSymbolAddress((void**)&waprojh, g_waprojh);
    cudaGetSymbolAddress((void**)&weprojT, g_weprojT);
    cudaGetSymbolAddress((void**)&wouth,   g_wouth);

    const dim3 blk(256);
    auto cvt = [&](const float* in, __half* o, long long n) {
        int n4 = (int)(n / 4);
        cvt_h<<<(n4 + 255) / 256, 256>>>(in, o, n4);
    };

    // launches 1-5 (so the ncu -s 5 window lands on L1, the big GEMM)
    cvt(x,      xh,     (long long)TOKENS * Dd);
    cvt(w_gate, wgateh, (long long)Hh * Dd);
    cvt(w_up,   wuph,   (long long)Hh * Dd);
    cvt(w_down, wdownh, (long long)Dd * Hh);
    cvt(w_pre,  wpreh,  (long long)Aa * Dd);

    // #6  L1: gate(f32) = x @ w_gate^T  [16384,2048]
    tc_gemm<0, false><<<dim3(Hh / 128, TOKENS / 128, 1), blk>>>(
        xh, wgateh, nullptr, gate, Dd, Dd, Dd, Hh, 0, 0, 0);

    // #7  L2: hidden(h) = silu(gate) * (x @ w_up^T)
    tc_gemm<2, true><<<dim3(Hh / 128, TOKENS / 128, 1), blk>>>(
        xh, wuph, gate, hidden, Dd, Dd, Dd, Hh, 0, 0, 0);

    // #8  L3: pre(f32) = x @ w_pre^T  [16384,128]
    tc_gemm<0, false><<<dim3(1, TOKENS / 128, 1), blk>>>(
        xh, wpreh, nullptr, pre, Dd, Dd, Dd, Aa, 0, 0, 0);

    cvt(w_post,  wposth,  (long long)Aa * Hh);
    cvt(w_aproj, waprojh, (long long)Hh * Aa);
    transpose_f2h<<<dim3(Aa / 32, Hh / 32, 1), dim3(32, 8)>>>(w_eproj, weprojT, Hh, Aa);
    cvt(w_out, wouth, (long long)Dd * Hh);

    // adapt_in = ln(pre) -> half
    ln_kernel<<<TOKENS, Aa>>>(pre, an_g, an_b, ain);

    // L5: aoutf = hidden @ w_post^T  [16384,128]
    tc_gemm<0, false><<<dim3(1, TOKENS / 128, 1), blk>>>(
        hidden, wposth, nullptr, aoutf, Hh, Hh, Hh, Aa, 0, 0, 0);

    // adapt_out = ln(aoutf) -> half
    ln_kernel<<<TOKENS, Aa>>>(aoutf, an_g, an_b, aouth);

    // L7: aw(h) = silu(clip(ain @ aout^T))  [8,2048,2048]
    tc_gemm<1, true><<<dim3(Ss / 128, Ss / 128, Bb), blk>>>(
        ain, aouth, nullptr, aw, Aa, Aa, Aa, Ss,
        (long long)Ss * Aa, (long long)Ss * Aa, (long long)Ss * Ss);

    // ainT[b] = ain[b]^T  [Aa,Ss]
    transpose_h<<<dim3(Aa / 32, Ss / 32, Bb), dim3(32, 8)>>>(
        ain, ainT, Ss, Aa, (long long)Ss * Aa, (long long)Aa * Ss);

    // L8: adapt(h) = aw @ ain  [8,2048,128]  (NT vs ainT)
    tc_gemm<0, true><<<dim3(1, Ss / 128, Bb), blk>>>(
        aw, ainT, nullptr, adapt, Ss, Ss, Ss, Aa,
        (long long)Ss * Ss, (long long)Aa * Ss, (long long)Ss * Aa);

    // L9: hidden(h) = hidden + 0.1 * adapt @ w_aproj^T  (in-place elementwise)
    tc_gemm<3, true><<<dim3(Hh / 128, TOKENS / 128, 1), blk>>>(
        adapt, waprojh, hidden, hidden, Aa, Aa, Aa, Hh, 0, 0, 0);

    // L10: out(f32) = hidden @ w_down^T  [16384,1024]
    tc_gemm<0, false><<<dim3(Dd / 128, TOKENS / 128, 1), blk>>>(
        hidden, wdownh, nullptr, out, Hh, Hh, Hh, Dd, 0, 0, 0);

    // L11: Wc(h) = w_out @ w_eproj  [Dd,Aa]  (NT vs weprojT)
    tc_gemm<0, true><<<dim3(Aa / 128, Dd / 128, 1), blk>>>(
        wouth, weprojT, nullptr, Wc, Hh, Hh, Hh, Aa, 0, 0, 0);

    // expert select + a = ln(pre @ w_exp[e]^T) -> half
    expert_kernel<<<TOKENS, Aa>>>(pre, ew, w_exp, eln_g, eln_b, abuf);

    // L13: out(f32) += 0.1 * abuf @ Wc^T
    tc_gemm<4, false><<<dim3(Dd / 128, TOKENS / 128, 1), blk>>>(
        abuf, Wc, out, out, Aa, Aa, Aa, Dd, 0, 0, 0);
}

// round 11
// speedup vs baseline: 3.3001x; 1.0202x over previous
#include <cuda_runtime.h>
#include <cuda_fp16.h>
#include <cstdint>
#include <math.h>

#define TOKENS 16384   // B*S
#define Dd 1024
#define Hh 2048
#define Aa 128
#define Ss 2048
#define Bb 8

// ---------------- scratch (device globals; no allocation allowed) ----------
__device__ float  g_gate  [(size_t)TOKENS * Hh];   // fp32 (silu input)
__device__ __half g_hidden[(size_t)TOKENS * Hh];
__device__ float  g_pre   [(size_t)TOKENS * Aa];   // fp32 (ln/expert input)
__device__ __half g_ain   [(size_t)TOKENS * Aa];
__device__ __half g_ainT  [(size_t)TOKENS * Aa];   // per-batch [Aa][Ss]
__device__ float  g_aoutf [(size_t)TOKENS * Aa];
__device__ __half g_aouth [(size_t)TOKENS * Aa];
__device__ __half g_adapt [(size_t)TOKENS * Aa];
__device__ __half g_abuf  [(size_t)TOKENS * Aa];
__device__ __half g_aw    [(size_t)Bb * Ss * Ss];  // 67 MB
__device__ __half g_W     [(size_t)Dd * Aa];       // w_out @ w_eproj
// fp16 copies of inputs
__device__ __half g_xh     [(size_t)TOKENS * Dd];
__device__ __half g_wuph   [(size_t)Hh * Dd];
__device__ __half g_wgateh [(size_t)Hh * Dd];
__device__ __half g_wdownh [(size_t)Dd * Hh];
__device__ __half g_wpreh  [(size_t)Aa * Dd];
__device__ __half g_wposth [(size_t)Aa * Hh];
__device__ __half g_waprojh[(size_t)Hh * Aa];
__device__ __half g_weprojT[(size_t)Aa * Hh];      // transposed
__device__ __half g_wouth  [(size_t)Dd * Hh];

// ---------------- helpers --------------------------------------------------
__device__ __forceinline__ float siluf(float x) { return x / (1.0f + __expf(-x)); }
__device__ __forceinline__ float clip5(float x) { return fminf(fmaxf(x, -5.0f), 5.0f); }

__device__ __forceinline__ unsigned smem_u32(const void* p) {
    unsigned a;
    asm("{ .reg .u64 t; cvta.to.shared.u64 t, %1; cvt.u32.u64 %0, t; }"
        : "=r"(a) : "l"(p));
    return a;
}

// ---------------- fp16 mma.sync GEMM (NT): C = A[M,K] @ B[N,K]^T -----------
// Tile (MT*32)x128, BK=32, 256 threads, 4-stage cp.async ring, ldmatrix frags.
// EPI 0: acc | 1: silu(clip(acc)) | 2: silu(Ef)*acc | 3: Eh+0.1*acc | 4: Ef+0.1*acc
// OUTH: store __half, else float.
#define SROW 40       // padded row stride in halves (conflict-free ldmatrix)
#define STAGES 4

template <int MT, int EPI, bool OUTH>
__global__ void __launch_bounds__(256, 2)
tc_gemm(const __half* __restrict__ Ag, const __half* __restrict__ Bg,
        const void* __restrict__ Eg, void* __restrict__ Cg,
        int K, int lda, int ldb, int ldc,
        long long sA, long long sB, long long sC)
{
    constexpr int TM = MT * 32;                    // 128 or 64
    extern __shared__ __half smem[];
    __half* sA_ = smem;                            // STAGES * TM * SROW
    __half* sB_ = smem + STAGES * TM * SROW;       // STAGES * 128 * SROW

    const int tid  = threadIdx.x;
    const int wid  = tid >> 5, lane = tid & 31;
    const int g    = lane >> 2, t = lane & 3;
    const int wm   = wid >> 2, wn = wid & 3;       // 2 x 4 warp grid
    const int m0   = blockIdx.y * TM, n0 = blockIdx.x * 128;

    const __half* A = Ag + (long long)blockIdx.z * sA;
    const __half* B = Bg + (long long)blockIdx.z * sB;

    float c[MT][4][4];
#pragma unroll
    for (int i = 0; i < MT; i++)
#pragma unroll
        for (int j = 0; j < 4; j++)
#pragma unroll
            for (int r = 0; r < 4; r++) c[i][j][r] = 0.0f;

    const int NC = K >> 5;

    auto fill = [&](int s, int ck) {
        const int k0 = ck << 5;
        // A: TM rows x 32 halves = TM*4 x 16B chunks
#pragma unroll
        for (int i = 0; i < (TM * 4) / 256; i++) {
            const int slot = tid + i * 256;
            const int row = slot >> 2, j = slot & 3;
            unsigned dst = smem_u32(&sA_[s * TM * SROW + row * SROW + j * 8]);
            const __half* src = A + (long long)(m0 + row) * lda + k0 + j * 8;
            asm volatile("cp.async.ca.shared.global [%0], [%1], 16;"
                         :: "r"(dst), "l"(src));
        }
#pragma unroll
        for (int i = 0; i < 2; i++) {
            const int slot = tid + i * 256;
            const int row = slot >> 2, j = slot & 3;
            unsigned dst = smem_u32(&sB_[s * 128 * SROW + row * SROW + j * 8]);
            const __half* src = B + (long long)(n0 + row) * ldb + k0 + j * 8;
            asm volatile("cp.async.ca.shared.global [%0], [%1], 16;"
                         :: "r"(dst), "l"(src));
        }
    };

    auto compute = [&](int s) {
        const unsigned baseA = smem_u32(&sA_[s * TM * SROW]);
        const unsigned baseB = smem_u32(&sB_[s * 128 * SROW]);
#pragma unroll
        for (int ks = 0; ks < 2; ks++) {
            unsigned a[MT][4], b[2][4];
#pragma unroll
            for (int mt = 0; mt < MT; mt++) {
                const int row = wm * (MT * 16) + mt * 16
                                + ((lane >> 3) & 1) * 8 + (lane & 7);
                const int kc  = ks * 16 + ((lane >> 4) & 1) * 8;
                unsigned addr = baseA + (unsigned)(row * SROW + kc) * 2u;
                asm volatile("ldmatrix.sync.aligned.m8n8.x4.shared.b16 "
                             "{%0,%1,%2,%3}, [%4];"
                             : "=r"(a[mt][0]), "=r"(a[mt][1]),
                               "=r"(a[mt][2]), "=r"(a[mt][3])
                             : "r"(addr));
            }
#pragma unroll
            for (int p = 0; p < 2; p++) {
                const int row = wn * 32 + p * 16 + ((lane >> 4) & 1) * 8 + (lane & 7);
                const int kc  = ks * 16 + ((lane >> 3) & 1) * 8;
                unsigned addr = baseB + (unsigned)(row * SROW + kc) * 2u;
                asm volatile("ldmatrix.sync.aligned.m8n8.x4.shared.b16 "
                             "{%0,%1,%2,%3}, [%4];"
                             : "=r"(b[p][0]), "=r"(b[p][1]),
                               "=r"(b[p][2]), "=r"(b[p][3])
                             : "r"(addr));
            }
#pragma unroll
            for (int mt = 0; mt < MT; mt++)
#pragma unroll
                for (int nt = 0; nt < 4; nt++) {
                    const int p = nt >> 1, q = (nt & 1) * 2;
                    asm volatile(
                        "mma.sync.aligned.m16n8k16.row.col.f32.f16.f16.f32 "
                        "{%0,%1,%2,%3}, {%4,%5,%6,%7}, {%8,%9}, {%0,%1,%2,%3};"
                        : "+f"(c[mt][nt][0]), "+f"(c[mt][nt][1]),
                          "+f"(c[mt][nt][2]), "+f"(c[mt][nt][3])
                        : "r"(a[mt][0]), "r"(a[mt][1]), "r"(a[mt][2]), "r"(a[mt][3]),
                          "r"(b[p][q]), "r"(b[p][q + 1]));
                }
        }
    };

    // ---- prologue: fill first STAGES-1 stages (empty commits keep count) ----
#pragma unroll
    for (int p = 0; p < STAGES - 1; p++) {
        if (p < NC) fill(p, p);
        asm volatile("cp.async.commit_group;" ::: "memory");
    }

    for (int ck = 0; ck < NC; ck++) {
        asm volatile("cp.async.wait_group %0;" :: "n"(STAGES - 2) : "memory");
        __syncthreads();
        compute(ck & (STAGES - 1));
        const int nf = ck + STAGES - 1;
        if (nf < NC) fill(nf & (STAGES - 1), nf);
        asm volatile("cp.async.commit_group;" ::: "memory");
    }

    // ---- epilogue ----
#pragma unroll
    for (int mt = 0; mt < MT; mt++) {
#pragma unroll
        for (int hf = 0; hf < 2; hf++) {
            const int r = m0 + wm * (MT * 16) + mt * 16 + g + hf * 8;
#pragma unroll
            for (int nt = 0; nt < 4; nt++) {
                const int col = n0 + wn * 32 + nt * 8 + 2 * t;
                const long long off = (long long)r * ldc + col
                                      + (long long)blockIdx.z * sC;
                float v0 = c[mt][nt][hf * 2 + 0];
                float v1 = c[mt][nt][hf * 2 + 1];
                if (EPI == 1) {
                    v0 = siluf(clip5(v0)); v1 = siluf(clip5(v1));
                } else if (EPI == 2) {
                    float2 e = *(const float2*)((const float*)Eg + off);
                    v0 *= siluf(e.x); v1 *= siluf(e.y);
                } else if (EPI == 3) {
                    __half2 e = *(const __half2*)((const __half*)Eg + off);
                    v0 = __half2float(e.x) + 0.1f * v0;
                    v1 = __half2float(e.y) + 0.1f * v1;
                } else if (EPI == 4) {
                    float2 e = *(const float2*)((const float*)Eg + off);
                    v0 = e.x + 0.1f * v0; v1 = e.y + 0.1f * v1;
                }
                if (OUTH) {
                    *(__half2*)((__half*)Cg + off) = __floats2half2_rn(v0, v1);
                } else {
                    *(float2*)((float*)Cg + off) = make_float2(v0, v1);
                }
            }
        }
    }
}

// smem sizes per MT
#define SMEM_MT4 (STAGES * (128 + 128) * SROW * 2)   // 81920 B
#define SMEM_MT2 (STAGES * (64 + 128) * SROW * 2)    // 61440 B

// ---------------- fused fp32 -> fp16 conversion (weights + x) --------------
// segments: x(16.7M), wgate(2M), wup(2M), wdown(2M), wpre(128K), wpost(256K),
//           waproj(256K), wout(2M)  — element counts /4 (float4 granules)
#define N4_X   ((TOKENS * (long long)Dd) / 4)
#define N4_HD  (((long long)Hh * Dd) / 4)
#define N4_AD  (((long long)Aa * Dd) / 4)
#define N4_AH  (((long long)Aa * Hh) / 4)
__global__ void cvt_all(const float* __restrict__ x,  __half* __restrict__ xo,
                        const float* __restrict__ w1, __half* __restrict__ o1,
                        const float* __restrict__ w2, __half* __restrict__ o2,
                        const float* __restrict__ w3, __half* __restrict__ o3,
                        const float* __restrict__ w4, __half* __restrict__ o4,
                        const float* __restrict__ w5, __half* __restrict__ o5,
                        const float* __restrict__ w6, __half* __restrict__ o6,
                        const float* __restrict__ w7, __half* __restrict__ o7)
{
    long long i = (long long)blockIdx.x * blockDim.x + threadIdx.x;
    const float* src; __half* dst; long long j = i;
    if      (j < N4_X)                 { src = x;  dst = xo; }
    else if ((j -= N4_X)  < N4_HD)     { src = w1; dst = o1; }
    else if ((j -= N4_HD) < N4_HD)     { src = w2; dst = o2; }
    else if ((j -= N4_HD) < N4_HD)     { src = w3; dst = o3; }
    else if ((j -= N4_HD) < N4_AD)     { src = w4; dst = o4; }
    else if ((j -= N4_AD) < N4_AH)     { src = w5; dst = o5; }
    else if ((j -= N4_AH) < N4_AH)     { src = w6; dst = o6; }
    else if ((j -= N4_AH) < N4_HD)     { src = w7; dst = o7; }
    else return;
    float4 v = ((const float4*)src)[j];
    ((__half2*)dst)[2 * j]     = __floats2half2_rn(v.x, v.y);
    ((__half2*)dst)[2 * j + 1] = __floats2half2_rn(v.z, v.w);
}
#define CVT_TOTAL4 (N4_X + 4 * N4_HD + N4_AD + 2 * N4_AH)

// ---------------- transposes ------------------------------------------------
__global__ void transpose_f2h(const float* __restrict__ in, __half* __restrict__ out,
                              int R, int C)
{
    __shared__ __half tile[32][33];
    const int c0 = blockIdx.x * 32, r0 = blockIdx.y * 32;
    const int tx = threadIdx.x, ty = threadIdx.y;
#pragma unroll
    for (int j = 0; j < 32; j += 8)
        tile[ty + j][tx] = __float2half_rn(in[(long long)(r0 + ty + j) * C + c0 + tx]);
    __syncthreads();
#pragma unroll
    for (int j = 0; j < 32; j += 8)
        out[(long long)(c0 + ty + j) * R + r0 + tx] = tile[tx][ty + j];
}

__global__ void transpose_h(const __half* __restrict__ in, __half* __restrict__ out,
                            int R, int C, long long sIn, long long sOut)
{
    __shared__ __half tile[32][33];
    const __half* ip = in + (long long)blockIdx.z * sIn;
    __half*       op = out + (long long)blockIdx.z * sOut;
    const int c0 = blockIdx.x * 32, r0 = blockIdx.y * 32;
    const int tx = threadIdx.x, ty = threadIdx.y;
#pragma unroll
    for (int j = 0; j < 32; j += 8)
        tile[ty + j][tx] = ip[(long long)(r0 + ty + j) * C + c0 + tx];
    __syncthreads();
#pragma unroll
    for (int j = 0; j < 32; j += 8)
        op[(long long)(c0 + ty + j) * R + r0 + tx] = tile[tx][ty + j];
}

// ---------------- LayerNorm over rows of length 128 (half out) -------------
__global__ void ln_kernel(const float* __restrict__ in,
                          const float* __restrict__ g,
                          const float* __restrict__ b,
                          __half* __restrict__ out)
{
    const int row = blockIdx.x;
    const int c = threadIdx.x;
    const float v = in[(long long)row * Aa + c];
    float s = v, s2 = v * v;
#pragma unroll
    for (int o = 16; o > 0; o >>= 1) {
        s  += __shfl_xor_sync(0xffffffffu, s,  o);
        s2 += __shfl_xor_sync(0xffffffffu, s2, o);
    }
    __shared__ float ps[4], ps2[4];
    const int w = c >> 5, l = c & 31;
    if (l == 0) { ps[w] = s; ps2[w] = s2; }
    __syncthreads();
    const float ts  = ps[0] + ps[1] + ps[2] + ps[3];
    const float ts2 = ps2[0] + ps2[1] + ps2[2] + ps2[3];
    const float m   = ts * (1.0f / 128.0f);
    const float var = ts2 * (1.0f / 128.0f) - m * m;
    out[(long long)row * Aa + c] =
        __float2half_rn((v - m) * rsqrtf(var + 1e-5f) * g[c] + b[c]);
}

// ---------------- expert select + a = ln(pre @ w_exp[e]^T) -----------------
__global__ void expert_kernel(const float* __restrict__ pre,
                              const float* __restrict__ ew,
                              const float* __restrict__ w_exp,
                              const float* __restrict__ eg,
                              const float* __restrict__ eb,
                              __half* __restrict__ abuf)
{
    const int token = blockIdx.x;
    const int c = threadIdx.x;

    int e = -1;
#pragma unroll
    for (int i = 0; i < 8; i++)
        if (ew[(long long)token * 8 + i] > 0.0f) e = i;

    if (e < 0) { abuf[(long long)token * Aa + c] = __float2half_rn(0.0f); return; }

    __shared__ float sp[Aa];
    sp[c] = pre[(long long)token * Aa + c];
    __syncthreads();

    const float* wrow = w_exp + ((long long)e * Aa + c) * Aa;
    float tacc = 0.0f;
#pragma unroll 8
    for (int a = 0; a < Aa; a++) tacc += sp[a] * wrow[a];

    float s = tacc, s2 = tacc * tacc;
#pragma unroll
    for (int o = 16; o > 0; o >>= 1) {
        s  += __shfl_xor_sync(0xffffffffu, s,  o);
        s2 += __shfl_xor_sync(0xffffffffu, s2, o);
    }
    __shared__ float ps[4], ps2[4];
    const int w = c >> 5, l = c & 31;
    if (l == 0) { ps[w] = s; ps2[w] = s2; }
    __syncthreads();
    const float ts  = ps[0] + ps[1] + ps[2] + ps[3];
    const float ts2 = ps2[0] + ps2[1] + ps2[2] + ps2[3];
    const float m   = ts * (1.0f / 128.0f);
    const float var = ts2 * (1.0f / 128.0f) - m * m;
    abuf[(long long)token * Aa + c] = __float2half_rn(
        (tacc - m) * rsqrtf(var + 1e-5f) * eg[(long long)e * Aa + c]
        + eb[(long long)e * Aa + c]);
}

// ---------------- launcher --------------------------------------------------
extern "C" void kernel_launch(void* const* d_in, const int* in_sizes, int n_in,
                              void* d_out, int out_size)
{
    const float* x       = (const float*)d_in[0];
    const float* ew      = (const float*)d_in[1];
    const float* w_up    = (const float*)d_in[2];
    const float* w_gate  = (const float*)d_in[3];
    const float* w_down  = (const float*)d_in[4];
    const float* w_pre   = (const float*)d_in[5];
    const float* w_post  = (const float*)d_in[6];
    const float* an_g    = (const float*)d_in[7];
    const float* an_b    = (const float*)d_in[8];
    const float* w_aproj = (const float*)d_in[9];
    const float* w_exp   = (const float*)d_in[10];
    const float* eln_g   = (const float*)d_in[11];
    const float* eln_b   = (const float*)d_in[12];
    const float* w_eproj = (const float*)d_in[13];
    const float* w_out   = (const float*)d_in[14];
    float* out = (float*)d_out;

    float *gate, *pre, *aoutf;
    __half *hidden, *ain, *ainT, *aouth, *adapt, *abuf, *aw, *Wc;
    __half *xh, *wuph, *wgateh, *wdownh, *wpreh, *wposth, *waprojh, *weprojT, *wouth;
    cudaGetSymbolAddress((void**)&gate,    g_gate);
    cudaGetSymbolAddress((void**)&hidden,  g_hidden);
    cudaGetSymbolAddress((void**)&pre,     g_pre);
    cudaGetSymbolAddress((void**)&ain,     g_ain);
    cudaGetSymbolAddress((void**)&ainT,    g_ainT);
    cudaGetSymbolAddress((void**)&aoutf,   g_aoutf);
    cudaGetSymbolAddress((void**)&aouth,   g_aouth);
    cudaGetSymbolAddress((void**)&adapt,   g_adapt);
    cudaGetSymbolAddress((void**)&abuf,    g_abuf);
    cudaGetSymbolAddress((void**)&aw,      g_aw);
    cudaGetSymbolAddress((void**)&Wc,      g_W);
    cudaGetSymbolAddress((void**)&xh,      g_xh);
    cudaGetSymbolAddress((void**)&wuph,    g_wuph);
    cudaGetSymbolAddress((void**)&wgateh,  g_wgateh);
    cudaGetSymbolAddress((void**)&wdownh,  g_wdownh);
    cudaGetSymbolAddress((void**)&wpreh,   g_wpreh);
    cudaGetSymbolAddress((void**)&wposth,  g_wposth);
    cudaGetSymbolAddress((void**)&waprojh, g_waprojh);
    cudaGetSymbolAddress((void**)&weprojT, g_weprojT);
    cudaGetSymbolAddress((void**)&wouth,   g_wouth);

    // dynamic-SMEM opt-in for every tc_gemm instantiation used
    cudaFuncSetAttribute(tc_gemm<4, 0, false>, cudaFuncAttributeMaxDynamicSharedMemorySize, SMEM_MT4);
    cudaFuncSetAttribute(tc_gemm<4, 2, true>,  cudaFuncAttributeMaxDynamicSharedMemorySize, SMEM_MT4);
    cudaFuncSetAttribute(tc_gemm<4, 1, true>,  cudaFuncAttributeMaxDynamicSharedMemorySize, SMEM_MT4);
    cudaFuncSetAttribute(tc_gemm<4, 3, true>,  cudaFuncAttributeMaxDynamicSharedMemorySize, SMEM_MT4);
    cudaFuncSetAttribute(tc_gemm<4, 4, false>, cudaFuncAttributeMaxDynamicSharedMemorySize, SMEM_MT4);
    cudaFuncSetAttribute(tc_gemm<2, 0, false>, cudaFuncAttributeMaxDynamicSharedMemorySize, SMEM_MT2);
    cudaFuncSetAttribute(tc_gemm<2, 0, true>,  cudaFuncAttributeMaxDynamicSharedMemorySize, SMEM_MT2);

    const dim3 blk(256);

    // #1: all fp32->fp16 conversions in one kernel
    cvt_all<<<(unsigned)((CVT_TOTAL4 + 255) / 256), 256>>>(
        x, xh, w_gate, wgateh, w_up, wuph, w_down, wdownh,
        w_pre, wpreh, w_post, wposth, w_aproj, waprojh, w_out, wouth);

    // #2: w_eproj round+transpose -> [Aa][Hh]
    transpose_f2h<<<dim3(Aa / 32, Hh / 32, 1), dim3(32, 8)>>>(w_eproj, weprojT, Hh, Aa);

    // #3  L1: gate(f32) = x @ w_gate^T  [16384,2048]
    tc_gemm<4, 0, false><<<dim3(Hh / 128, TOKENS / 128, 1), blk, SMEM_MT4>>>(
        xh, wgateh, nullptr, gate, Dd, Dd, Dd, Hh, 0, 0, 0);

    // #4  L2: hidden(h) = silu(gate) * (x @ w_up^T)
    tc_gemm<4, 2, true><<<dim3(Hh / 128, TOKENS / 128, 1), blk, SMEM_MT4>>>(
        xh, wuph, gate, hidden, Dd, Dd, Dd, Hh, 0, 0, 0);

    // #5  L3: pre(f32) = x @ w_pre^T  [16384,128]  (MT=2: 256 blocks)
    tc_gemm<2, 0, false><<<dim3(1, TOKENS / 64, 1), blk, SMEM_MT2>>>(
        xh, wpreh, nullptr, pre, Dd, Dd, Dd, Aa, 0, 0, 0);

    // #6  L5: aoutf = hidden @ w_post^T  [16384,128]
    tc_gemm<2, 0, false><<<dim3(1, TOKENS / 64, 1), blk, SMEM_MT2>>>(
        hidden, wposth, nullptr, aoutf, Hh, Hh, Hh, Aa, 0, 0, 0);

    // adapt_in = ln(pre) -> half
    ln_kernel<<<TOKENS, Aa>>>(pre, an_g, an_b, ain);

    // adapt_out = ln(aoutf) -> half
    ln_kernel<<<TOKENS, Aa>>>(aoutf, an_g, an_b, aouth);

    // L7: aw(h) = silu(clip(ain @ aout^T))  [8,2048,2048]
    tc_gemm<4, 1, true><<<dim3(Ss / 128, Ss / 128, Bb), blk, SMEM_MT4>>>(
        ain, aouth, nullptr, aw, Aa, Aa, Aa, Ss,
        (long long)Ss * Aa, (long long)Ss * Aa, (long long)Ss * Ss);

    // ainT[b] = ain[b]^T  [Aa,Ss]
    transpose_h<<<dim3(Aa / 32, Ss / 32, Bb), dim3(32, 8)>>>(
        ain, ainT, Ss, Aa, (long long)Ss * Aa, (long long)Aa * Ss);

    // L8: adapt(h) = aw @ ain  [8,2048,128]  (NT vs ainT, MT=2: 256 blocks)
    tc_gemm<2, 0, true><<<dim3(1, Ss / 64, Bb), blk, SMEM_MT2>>>(
        aw, ainT, nullptr, adapt, Ss, Ss, Ss, Aa,
        (long long)Ss * Ss, (long long)Aa * Ss, (long long)Ss * Aa);

    // L9: hidden(h) = hidden + 0.1 * adapt @ w_aproj^T  (in-place elementwise)
    tc_gemm<4, 3, true><<<dim3(Hh / 128, TOKENS / 128, 1), blk, SMEM_MT4>>>(
        adapt, waprojh, hidden, hidden, Aa, Aa, Aa, Hh, 0, 0, 0);

    // L10: out(f32) = hidden @ w_down^T  [16384,1024]
    tc_gemm<4, 0, false><<<dim3(Dd / 128, TOKENS / 128, 1), blk, SMEM_MT4>>>(
        hidden, wdownh, nullptr, out, Hh, Hh, Hh, Dd, 0, 0, 0);

    // L11: Wc(h) = w_out @ w_eproj  [Dd,Aa]  (NT vs weprojT, MT=2: 16 blocks)
    tc_gemm<2, 0, true><<<dim3(1, Dd / 64, 1), blk, SMEM_MT2>>>(
        wouth, weprojT, nullptr, Wc, Hh, Hh, Hh, Aa, 0, 0, 0);

    // expert select + a = ln(pre @ w_exp[e]^T) -> half
    expert_kernel<<<TOKENS, Aa>>>(pre, ew, w_exp, eln_g, eln_b, abuf);

    // L13: out(f32) += 0.1 * abuf @ Wc^T
    tc_gemm<4, 4, false><<<dim3(Dd / 128, TOKENS / 128, 1), blk, SMEM_MT4>>>(
        abuf, Wc, out, out, Aa, Aa, Aa, Dd, 0, 0, 0);
}